// round 8
// baseline (speedup 1.0000x reference)
#include <cuda_runtime.h>
#include <math.h>

// Problem constants (fixed by the reference setup)
#define BATCH    16
#define NANCH    36864      // 64*64*9
#define TPB      1024
#define SEG      36         // NANCH / TPB
#define TOPN     300
#define NGT      64
#define NPOS     64
#define NBUCK    8192       // top-13-bit score buckets
#define CAND_MAX 8192       // max candidates per tranche (bufA capacity)
#define TARGET   4096       // desired candidates in first tranche

typedef unsigned long long u64;
typedef unsigned int u32;

// Scratch (static device allocations — no runtime alloc)
__device__ float4 g_boxes[BATCH * NANCH];   // decoded (unclipped) boxes
__device__ u32    g_cum[BATCH * NBUCK];     // inclusive bucket prefix sums

// ---------------------------------------------------------------------------
// IoU exactly as reference: inter / (((areaA + areaB) - inter) + 1e-7)
// ---------------------------------------------------------------------------
__device__ __forceinline__ float iou_ref(float4 a, float4 b) {
    float yy1 = fmaxf(a.x, b.x);
    float xx1 = fmaxf(a.y, b.y);
    float yy2 = fminf(a.z, b.z);
    float xx2 = fminf(a.w, b.w);
    float ih  = fmaxf(yy2 - yy1, 0.0f);
    float iw  = fmaxf(xx2 - xx1, 0.0f);
    float inter = ih * iw;
    float areaA = (a.z - a.x) * (a.w - a.y);
    float areaB = (b.z - b.x) * (b.w - b.y);
    return inter / (((areaA + areaB) - inter) + 1e-7f);
}

// exclusive block scan of per-thread totals (1024 threads, 32 warps).
__device__ __forceinline__ u32 block_excl_scan(u32 run, int lane, int warp, u32* sWarpSum) {
    u32 x = run;
    #pragma unroll
    for (int off = 1; off < 32; off <<= 1) {
        u32 y = __shfl_up_sync(0xFFFFFFFFu, x, off);
        if (lane >= off) x += y;
    }
    if (lane == 31) sWarpSum[warp] = x;
    __syncthreads();
    if (warp == 0) {
        u32 s = sWarpSum[lane];
        #pragma unroll
        for (int off = 1; off < 32; off <<= 1) {
            u32 y = __shfl_up_sync(0xFFFFFFFFu, s, off);
            if (lane >= off) s += y;
        }
        sWarpSum[lane] = s;
    }
    __syncthreads();
    u32 warpOff = (warp == 0) ? 0u : sWarpSum[warp - 1];
    return warpOff + x - run;
}

// ---------------------------------------------------------------------------
// Kernel 1: decode deltas -> boxes (mirrors reference op order exactly)
// ---------------------------------------------------------------------------
__global__ void decode_kernel(const float4* __restrict__ deltas,
                              const float4* __restrict__ anchors) {
    int i = blockIdx.x * blockDim.x + threadIdx.x;
    if (i >= BATCH * NANCH) return;
    float4 a = anchors[i];
    float4 d = deltas[i];
    float ah  = a.z - a.x;
    float aw  = a.w - a.y;
    float acy = a.x + 0.5f * ah;
    float acx = a.y + 0.5f * aw;
    float h   = expf(d.z) * ah;
    float w   = expf(d.w) * aw;
    float cy  = d.x * ah + acy;
    float cx  = d.y * aw + acx;
    float y1  = cy - 0.5f * h;
    float x1  = cx - 0.5f * w;
    g_boxes[i] = make_float4(y1, x1, y1 + h, x1 + w);
}

// ---------------------------------------------------------------------------
// Kernel 2 (fused): histogram -> bucket-scatter + per-bucket insertion sort
// (replaces LSD radix) -> warp-window greedy scan -> RoI selection + output.
// One CTA per batch. Determinism: atomic intra-bucket order is erased by the
// per-bucket sort on the unique (score,idx) key.
// ---------------------------------------------------------------------------
__global__ __launch_bounds__(TPB, 1)
void nms_kernel(const float* __restrict__ labels,
                const float4* __restrict__ gt,
                float* __restrict__ out,
                int out_size) {
    extern __shared__ char dynsmem[];
    u64* bufA    = (u64*)dynsmem;                  // 64 KB: sorted candidates
    u32* regionC = (u32*)(dynsmem + 65536);        // 32 KB: hist / counters / select scratch

    __shared__ float4 sKept[TOPN];    // unclipped kept boxes (for suppression)
    __shared__ float4 sNms[TOPN];     // clipped kept boxes  (NMS output)
    __shared__ float4 sGtb[NGT];
    __shared__ u32    sWarpSum[32];
    __shared__ int    sKc;
    __shared__ int    sKlo, sKhi;

    const int b    = blockIdx.x;
    const int t    = threadIdx.x;
    const int lane = t & 31;
    const int warp = t >> 5;

    const float*  sc    = labels  + (size_t)b * NANCH;
    const float4* boxes = g_boxes + (size_t)b * NANCH;
    u32*          cum   = g_cum   + (size_t)b * NBUCK;

    // ---------------- phase 1: bucket histogram + prefix sums ----------------
    u32* hist = regionC;
    for (int i = t; i < NBUCK; i += TPB) hist[i] = 0u;
    __syncthreads();
    #pragma unroll
    for (int k = 0; k < SEG; k++) {
        u32 bits = ~__float_as_uint(sc[k * TPB + t]);   // coalesced
        atomicAdd(&hist[bits >> 19], 1u);               // ascending bucket = score desc
    }
    __syncthreads();
    {   // inclusive prefix over NBUCK buckets (8 contiguous per thread)
        u32 loc[8], run = 0;
        #pragma unroll
        for (int i = 0; i < 8; i++) { run += hist[t * 8 + i]; loc[i] = run; }
        u32 excl = block_excl_scan(run, lane, warp, sWarpSum);
        #pragma unroll
        for (int i = 0; i < 8; i++) hist[t * 8 + i] = loc[i] + excl;
        __syncthreads();
        for (int i = t; i < NBUCK; i += TPB) cum[i] = hist[i];  // persist (regionC reused)
        __syncthreads();
    }

    // ---------------- tranche loop ----------------
    int kc   = 0;
    int curK = -1;
    u32 base = 0;

    while (kc < TOPN) {
        // --- choose K*: smallest j with >=TARGET candidates, capped at CAND_MAX ---
        if (t == 0) { sKlo = NBUCK; sKhi = NBUCK; }
        __syncthreads();
        for (int i = t; i < NBUCK; i += TPB) {
            if (i > curK) {
                u32 c = cum[i] - base;
                if (c >= (u32)TARGET)   atomicMin(&sKlo, i);
                if (c >  (u32)CAND_MAX) atomicMin(&sKhi, i);
            }
        }
        __syncthreads();
        int Kstar = min(sKlo, sKhi - 1);
        if (Kstar > NBUCK - 1) Kstar = NBUCK - 1;
        if (Kstar < curK + 1)  Kstar = curK + 1;   // pathological giant bucket (unreachable)
        int C = (int)(cum[Kstar] - base);          // exact tranche size (<= CAND_MAX)

        // --- init per-bucket write cursors to bucket start offsets ---
        u32* cnt = regionC;   // 8192 cursors
        for (int i = t; i < NBUCK; i += TPB)
            cnt[i] = (i > 0 ? cum[i - 1] : 0u) - base;   // only used for in-range buckets
        __syncthreads();

        // --- scatter candidates directly to bucket-grouped positions (coalesced read) ---
        #pragma unroll
        for (int k = 0; k < SEG; k++) {
            int e = k * TPB + t;
            u32 bits = ~__float_as_uint(sc[e]);
            int kb = (int)(bits >> 19);
            if (kb > curK && kb <= Kstar) {
                u32 pos = atomicAdd(&cnt[kb], 1u);       // pos < C guaranteed by Kstar cap
                bufA[pos] = ((u64)bits << 16) | (u32)e;
            }
        }
        __syncthreads();

        // --- per-bucket insertion sort on unique u64 key -> deterministic order ---
        for (int i = t; i < NBUCK; i += TPB) {
            if (i > curK && i <= Kstar) {
                int s = (int)((i > 0 ? cum[i - 1] : 0u) - base);
                int epos = (int)(cum[i] - base);
                for (int p = s + 1; p < epos; p++) {
                    u64 key = bufA[p];
                    int j = p - 1;
                    while (j >= s && bufA[j] > key) { bufA[j + 1] = bufA[j]; j--; }
                    bufA[j + 1] = key;
                }
            }
        }
        __syncthreads();
        // bufA[0..C): (score desc, idx asc)

        // --- warp-window greedy scan: 1 block barrier per 32 candidates ---
        for (int cb = 0; cb < C && kc < TOPN; cb += TPB) {
            int  pos  = cb + t;
            bool have = pos < C;
            u64  it   = have ? bufA[pos] : ~0ull;
            int  e    = (int)(it & 0xFFFFull);
            float4 myBox = make_float4(0.f, 0.f, 0.f, 0.f);
            if (have) myBox = boxes[e];
            bool alive = have;
            if (alive) {
                for (int j = 0; j < kc; j++)
                    if (iou_ref(sKept[j], myBox) >= 0.5f) { alive = false; break; }
            }
            __syncthreads();   // sKept stable + alive computed before windows start

            for (int w = 0; w < 32 && kc < TOPN; w++) {
                if (warp == w) {
                    // intra-warp serial greedy over this window (sorted order)
                    u32 m = __ballot_sync(0xFFFFFFFFu, alive);
                    int kloc = kc;
                    while (m && kloc < TOPN) {
                        int win = __ffs((int)m) - 1;
                        float4 wb;
                        wb.x = __shfl_sync(0xFFFFFFFFu, myBox.x, win);
                        wb.y = __shfl_sync(0xFFFFFFFFu, myBox.y, win);
                        wb.z = __shfl_sync(0xFFFFFFFFu, myBox.z, win);
                        wb.w = __shfl_sync(0xFFFFFFFFu, myBox.w, win);
                        if (lane == win) {
                            sKept[kloc] = myBox;          // unclipped for suppression
                            float4 c;
                            c.x = fminf(fmaxf(myBox.x, 0.0f), 1.0f);
                            c.y = fminf(fmaxf(myBox.y, 0.0f), 1.0f);
                            c.z = fminf(fmaxf(myBox.z, 0.0f), 1.0f);
                            c.w = fminf(fmaxf(myBox.w, 0.0f), 1.0f);
                            sNms[kloc] = c;
                            alive = false;                 // explicit self-suppress
                        } else if (alive && iou_ref(wb, myBox) >= 0.5f) {
                            alive = false;
                        }
                        kloc++;
                        m = __ballot_sync(0xFFFFFFFFu, alive);
                    }
                    if (lane == 0) sKc = kloc;
                }
                __syncthreads();                           // publish sKept[kc..nk), sKc
                int nk = sKc;
                if (warp > w && alive) {                   // later windows: self-suppress vs new kept
                    for (int j = kc; j < nk; j++)
                        if (iou_ref(sKept[j], myBox) >= 0.5f) { alive = false; break; }
                }
                kc = nk;
            }
        }

        // --- next tranche (exact refill) ---
        if (Kstar >= NBUCK - 1) break;                     // all boxes consumed
        curK = Kstar;
        base = cum[Kstar];
        __syncthreads();
    }

    // zero-fill remaining (invalid) NMS slots
    for (int s = kc + t; s < TOPN; s += TPB)
        sNms[s] = make_float4(0.f, 0.f, 0.f, 0.f);

    // ---------------- fused RoI selection (former select_kernel) ----------------
    float* merged = (float*)regionC;           // TOPN floats
    int*   gbest  = (int*)(regionC + 512);     // TOPN ints

    if (t < NGT) sGtb[t] = gt[b * NGT + t];
    __syncthreads();

    if (t < TOPN) {
        float4 A = sNms[t];
        float areaA = (A.z - A.x) * (A.w - A.y);
        float best = -INFINITY; int bj = 0;
        #pragma unroll 4
        for (int j = 0; j < NGT; j++) {
            float4 G = sGtb[j];
            float yy1 = fmaxf(A.x, G.x);
            float xx1 = fmaxf(A.y, G.y);
            float yy2 = fminf(A.z, G.z);
            float xx2 = fminf(A.w, G.w);
            float ih  = fmaxf(yy2 - yy1, 0.0f);
            float iw  = fmaxf(xx2 - xx1, 0.0f);
            float inter = ih * iw;
            float areaG = (G.z - G.x) * (G.w - G.y);
            float iou   = inter / (((areaA + areaG) - inter) + 1e-7f);
            if (iou > best) { best = iou; bj = j; }   // strict > == first occurrence
        }
        merged[t] = best;
        gbest[t]  = bj;
    }
    __syncthreads();

    if (t < TOPN) {
        float mv = merged[t];
        int rank = 0;
        for (int q = 0; q < TOPN; q++) {
            float qv = merged[q];
            rank += (qv > mv) || (qv == mv && q < t);   // stable: matches jnp.argsort
        }
        if (rank < NPOS) {
            float4 A = sNms[t];
            float* o = out + (size_t)b * 512 + (size_t)rank * 4;
            o[0] = A.x; o[1] = A.y; o[2] = A.z; o[3] = A.w;
            if (out_size >= BATCH * 512 + BATCH * NGT) {
                out[BATCH * 512 + b * NGT + rank] = (float)gbest[t];
            }
        }
    }

    // negatives: rows 64..127 are zeros
    for (int i = t; i < 256; i += TPB)
        out[(size_t)b * 512 + 256 + i] = 0.0f;
}

// ---------------------------------------------------------------------------
extern "C" void kernel_launch(void* const* d_in, const int* in_sizes, int n_in,
                              void* d_out, int out_size) {
    const float4* deltas  = (const float4*)d_in[0];  // (B,64,64,36)
    const float*  labels  = (const float*)d_in[1];   // (B,64,64,9)
    const float4* anchors = (const float4*)d_in[2];  // (B,N,4)
    const float4* gt      = (const float4*)d_in[3];  // (B,64,4)
    float* out = (float*)d_out;

    (void)in_sizes; (void)n_in;

    static_assert(SEG * TPB == NANCH, "tiling must cover N exactly");

    size_t smem = 98304;   // bufA(64K) + regionC(32K)
    cudaFuncSetAttribute(nms_kernel, cudaFuncAttributeMaxDynamicSharedMemorySize, (int)smem);

    decode_kernel<<<(BATCH * NANCH + 255) / 256, 256>>>(deltas, anchors);
    nms_kernel<<<BATCH, TPB, smem>>>(labels, gt, out, out_size);
}

// round 9
// speedup vs baseline: 91.8685x; 91.8685x over previous
#include <cuda_runtime.h>
#include <math.h>

// Problem constants (fixed by the reference setup)
#define BATCH    16
#define NANCH    36864      // 64*64*9
#define TPB      1024
#define SEG      36         // NANCH / TPB
#define TOPN     300
#define NGT      64
#define NPOS     64
#define NBUCK    8192       // value-uniform score buckets
#define CAND_MAX 8192       // max candidates per tranche (bufA capacity)
#define TARGET   4096       // desired candidates in first tranche

typedef unsigned long long u64;
typedef unsigned int u32;

// Scratch (static device allocations — no runtime alloc)
__device__ float4 g_boxes[BATCH * NANCH];   // decoded (unclipped) boxes
__device__ u32    g_cum[BATCH * NBUCK];     // inclusive bucket prefix sums

// ---------------------------------------------------------------------------
// Bucket on VALUE (uniform for uniform scores), descending: bucket 0 = highest.
// trunc(s*NBUCK) is monotone nondecreasing in s; equal s -> same bucket.
// ---------------------------------------------------------------------------
__device__ __forceinline__ int score_bucket(float s) {
    int i = (int)(s * (float)NBUCK);      // trunc toward zero: monotone overall
    i = max(0, min(NBUCK - 1, i));
    return (NBUCK - 1) - i;               // ascending bucket = descending score
}

// Total-order key: ascending key = descending score (sign-aware, any float range).
__device__ __forceinline__ u32 score_sortbits(float s) {
    u32 bb = __float_as_uint(s);
    u32 ord = bb ^ ((bb >> 31) ? 0xFFFFFFFFu : 0x80000000u);  // monotone in value
    return ~ord;                                              // ascending = value desc
}

// ---------------------------------------------------------------------------
// IoU exactly as reference: inter / (((areaA + areaB) - inter) + 1e-7)
// ---------------------------------------------------------------------------
__device__ __forceinline__ float iou_ref(float4 a, float4 b) {
    float yy1 = fmaxf(a.x, b.x);
    float xx1 = fmaxf(a.y, b.y);
    float yy2 = fminf(a.z, b.z);
    float xx2 = fminf(a.w, b.w);
    float ih  = fmaxf(yy2 - yy1, 0.0f);
    float iw  = fmaxf(xx2 - xx1, 0.0f);
    float inter = ih * iw;
    float areaA = (a.z - a.x) * (a.w - a.y);
    float areaB = (b.z - b.x) * (b.w - b.y);
    return inter / (((areaA + areaB) - inter) + 1e-7f);
}

// exclusive block scan of per-thread totals (1024 threads, 32 warps).
__device__ __forceinline__ u32 block_excl_scan(u32 run, int lane, int warp, u32* sWarpSum) {
    u32 x = run;
    #pragma unroll
    for (int off = 1; off < 32; off <<= 1) {
        u32 y = __shfl_up_sync(0xFFFFFFFFu, x, off);
        if (lane >= off) x += y;
    }
    if (lane == 31) sWarpSum[warp] = x;
    __syncthreads();
    if (warp == 0) {
        u32 s = sWarpSum[lane];
        #pragma unroll
        for (int off = 1; off < 32; off <<= 1) {
            u32 y = __shfl_up_sync(0xFFFFFFFFu, s, off);
            if (lane >= off) s += y;
        }
        sWarpSum[lane] = s;
    }
    __syncthreads();
    u32 warpOff = (warp == 0) ? 0u : sWarpSum[warp - 1];
    return warpOff + x - run;
}

// ---------------------------------------------------------------------------
// Kernel 1: decode deltas -> boxes (mirrors reference op order exactly)
// ---------------------------------------------------------------------------
__global__ void decode_kernel(const float4* __restrict__ deltas,
                              const float4* __restrict__ anchors) {
    int i = blockIdx.x * blockDim.x + threadIdx.x;
    if (i >= BATCH * NANCH) return;
    float4 a = anchors[i];
    float4 d = deltas[i];
    float ah  = a.z - a.x;
    float aw  = a.w - a.y;
    float acy = a.x + 0.5f * ah;
    float acx = a.y + 0.5f * aw;
    float h   = expf(d.z) * ah;
    float w   = expf(d.w) * aw;
    float cy  = d.x * ah + acy;
    float cx  = d.y * aw + acx;
    float y1  = cy - 0.5f * h;
    float x1  = cx - 0.5f * w;
    g_boxes[i] = make_float4(y1, x1, y1 + h, x1 + w);
}

// ---------------------------------------------------------------------------
// Kernel 2 (fused): value-bucket histogram -> scatter + tiny per-bucket
// insertion sort -> warp-window greedy scan -> RoI selection + output.
// One CTA per batch. Determinism: atomic intra-bucket order is erased by the
// per-bucket sort on the unique (score,idx) key.
// ---------------------------------------------------------------------------
__global__ __launch_bounds__(TPB, 1)
void nms_kernel(const float* __restrict__ labels,
                const float4* __restrict__ gt,
                float* __restrict__ out,
                int out_size) {
    extern __shared__ char dynsmem[];
    u64* bufA    = (u64*)dynsmem;                  // 64 KB: sorted candidates
    u32* regionC = (u32*)(dynsmem + 65536);        // 32 KB: hist / counters / select scratch

    __shared__ float4 sKept[TOPN];    // unclipped kept boxes (for suppression)
    __shared__ float4 sNms[TOPN];     // clipped kept boxes  (NMS output)
    __shared__ float4 sGtb[NGT];
    __shared__ u32    sWarpSum[32];
    __shared__ int    sKc;
    __shared__ int    sKlo, sKhi;

    const int b    = blockIdx.x;
    const int t    = threadIdx.x;
    const int lane = t & 31;
    const int warp = t >> 5;

    const float*  sc    = labels  + (size_t)b * NANCH;
    const float4* boxes = g_boxes + (size_t)b * NANCH;
    u32*          cum   = g_cum   + (size_t)b * NBUCK;

    // ---------------- phase 1: bucket histogram + prefix sums ----------------
    u32* hist = regionC;
    for (int i = t; i < NBUCK; i += TPB) hist[i] = 0u;
    __syncthreads();
    #pragma unroll
    for (int k = 0; k < SEG; k++) {
        int kb = score_bucket(sc[k * TPB + t]);         // coalesced read
        atomicAdd(&hist[kb], 1u);
    }
    __syncthreads();
    {   // inclusive prefix over NBUCK buckets (8 contiguous per thread)
        u32 loc[8], run = 0;
        #pragma unroll
        for (int i = 0; i < 8; i++) { run += hist[t * 8 + i]; loc[i] = run; }
        u32 excl = block_excl_scan(run, lane, warp, sWarpSum);
        #pragma unroll
        for (int i = 0; i < 8; i++) hist[t * 8 + i] = loc[i] + excl;
        __syncthreads();
        for (int i = t; i < NBUCK; i += TPB) cum[i] = hist[i];  // persist (regionC reused)
        __syncthreads();
    }

    // ---------------- tranche loop ----------------
    int kc   = 0;
    int curK = -1;
    u32 base = 0;

    while (kc < TOPN) {
        // --- choose K*: smallest j with >=TARGET candidates, capped at CAND_MAX ---
        if (t == 0) { sKlo = NBUCK; sKhi = NBUCK; }
        __syncthreads();
        for (int i = t; i < NBUCK; i += TPB) {
            if (i > curK) {
                u32 c = cum[i] - base;
                if (c >= (u32)TARGET)   atomicMin(&sKlo, i);
                if (c >  (u32)CAND_MAX) atomicMin(&sKhi, i);
            }
        }
        __syncthreads();
        int Kstar = min(sKlo, sKhi - 1);
        if (Kstar > NBUCK - 1) Kstar = NBUCK - 1;
        if (Kstar < curK + 1)  Kstar = curK + 1;   // pathological giant bucket
        int C = (int)(cum[Kstar] - base);          // exact tranche size (<= CAND_MAX)

        // --- init per-bucket write cursors to bucket start offsets ---
        u32* cnt = regionC;   // 8192 cursors
        for (int i = t; i < NBUCK; i += TPB)
            cnt[i] = (i > 0 ? cum[i - 1] : 0u) - base;   // only used for in-range buckets
        __syncthreads();

        // --- scatter candidates directly to bucket-grouped positions (coalesced read) ---
        #pragma unroll
        for (int k = 0; k < SEG; k++) {
            int e = k * TPB + t;
            float s = sc[e];
            int kb = score_bucket(s);
            if (kb > curK && kb <= Kstar) {
                u32 pos = atomicAdd(&cnt[kb], 1u);       // pos < C guaranteed by Kstar cap
                bufA[pos] = ((u64)score_sortbits(s) << 16) | (u32)e;
            }
        }
        __syncthreads();

        // --- per-bucket insertion sort on unique u64 key -> deterministic order.
        //     Value-uniform buckets: mean ~4.5 items, max ~20 -> O(k^2) trivial. ---
        for (int i = t; i < NBUCK; i += TPB) {
            if (i > curK && i <= Kstar) {
                int s = (int)((i > 0 ? cum[i - 1] : 0u) - base);
                int epos = (int)(cum[i] - base);
                for (int p = s + 1; p < epos; p++) {
                    u64 key = bufA[p];
                    int j = p - 1;
                    while (j >= s && bufA[j] > key) { bufA[j + 1] = bufA[j]; j--; }
                    bufA[j + 1] = key;
                }
            }
        }
        __syncthreads();
        // bufA[0..C): (score desc, idx asc)

        // --- warp-window greedy scan: 1 block barrier per 32 candidates ---
        for (int cb = 0; cb < C && kc < TOPN; cb += TPB) {
            int  pos  = cb + t;
            bool have = pos < C;
            u64  it   = have ? bufA[pos] : ~0ull;
            int  e    = (int)(it & 0xFFFFull);
            float4 myBox = make_float4(0.f, 0.f, 0.f, 0.f);
            if (have) myBox = boxes[e];
            bool alive = have;
            if (alive) {
                for (int j = 0; j < kc; j++)
                    if (iou_ref(sKept[j], myBox) >= 0.5f) { alive = false; break; }
            }
            __syncthreads();   // sKept stable + alive computed before windows start

            for (int w = 0; w < 32 && kc < TOPN; w++) {
                if (warp == w) {
                    // intra-warp serial greedy over this window (sorted order)
                    u32 m = __ballot_sync(0xFFFFFFFFu, alive);
                    int kloc = kc;
                    while (m && kloc < TOPN) {
                        int win = __ffs((int)m) - 1;
                        float4 wb;
                        wb.x = __shfl_sync(0xFFFFFFFFu, myBox.x, win);
                        wb.y = __shfl_sync(0xFFFFFFFFu, myBox.y, win);
                        wb.z = __shfl_sync(0xFFFFFFFFu, myBox.z, win);
                        wb.w = __shfl_sync(0xFFFFFFFFu, myBox.w, win);
                        if (lane == win) {
                            sKept[kloc] = myBox;          // unclipped for suppression
                            float4 c;
                            c.x = fminf(fmaxf(myBox.x, 0.0f), 1.0f);
                            c.y = fminf(fmaxf(myBox.y, 0.0f), 1.0f);
                            c.z = fminf(fmaxf(myBox.z, 0.0f), 1.0f);
                            c.w = fminf(fmaxf(myBox.w, 0.0f), 1.0f);
                            sNms[kloc] = c;
                            alive = false;                 // explicit self-suppress
                        } else if (alive && iou_ref(wb, myBox) >= 0.5f) {
                            alive = false;
                        }
                        kloc++;
                        m = __ballot_sync(0xFFFFFFFFu, alive);
                    }
                    if (lane == 0) sKc = kloc;
                }
                __syncthreads();                           // publish sKept[kc..nk), sKc
                int nk = sKc;
                if (warp > w && alive) {                   // later windows: self-suppress vs new kept
                    for (int j = kc; j < nk; j++)
                        if (iou_ref(sKept[j], myBox) >= 0.5f) { alive = false; break; }
                }
                kc = nk;
            }
        }

        // --- next tranche (exact refill) ---
        if (Kstar >= NBUCK - 1) break;                     // all boxes consumed
        curK = Kstar;
        base = cum[Kstar];
        __syncthreads();
    }

    // zero-fill remaining (invalid) NMS slots
    for (int s = kc + t; s < TOPN; s += TPB)
        sNms[s] = make_float4(0.f, 0.f, 0.f, 0.f);

    // ---------------- fused RoI selection (former select_kernel) ----------------
    float* merged = (float*)regionC;           // TOPN floats
    int*   gbest  = (int*)(regionC + 512);     // TOPN ints

    if (t < NGT) sGtb[t] = gt[b * NGT + t];
    __syncthreads();

    if (t < TOPN) {
        float4 A = sNms[t];
        float areaA = (A.z - A.x) * (A.w - A.y);
        float best = -INFINITY; int bj = 0;
        #pragma unroll 4
        for (int j = 0; j < NGT; j++) {
            float4 G = sGtb[j];
            float yy1 = fmaxf(A.x, G.x);
            float xx1 = fmaxf(A.y, G.y);
            float yy2 = fminf(A.z, G.z);
            float xx2 = fminf(A.w, G.w);
            float ih  = fmaxf(yy2 - yy1, 0.0f);
            float iw  = fmaxf(xx2 - xx1, 0.0f);
            float inter = ih * iw;
            float areaG = (G.z - G.x) * (G.w - G.y);
            float iou   = inter / (((areaA + areaG) - inter) + 1e-7f);
            if (iou > best) { best = iou; bj = j; }   // strict > == first occurrence
        }
        merged[t] = best;
        gbest[t]  = bj;
    }
    __syncthreads();

    if (t < TOPN) {
        float mv = merged[t];
        int rank = 0;
        for (int q = 0; q < TOPN; q++) {
            float qv = merged[q];
            rank += (qv > mv) || (qv == mv && q < t);   // stable: matches jnp.argsort
        }
        if (rank < NPOS) {
            float4 A = sNms[t];
            float* o = out + (size_t)b * 512 + (size_t)rank * 4;
            o[0] = A.x; o[1] = A.y; o[2] = A.z; o[3] = A.w;
            if (out_size >= BATCH * 512 + BATCH * NGT) {
                out[BATCH * 512 + b * NGT + rank] = (float)gbest[t];
            }
        }
    }

    // negatives: rows 64..127 are zeros
    for (int i = t; i < 256; i += TPB)
        out[(size_t)b * 512 + 256 + i] = 0.0f;
}

// ---------------------------------------------------------------------------
extern "C" void kernel_launch(void* const* d_in, const int* in_sizes, int n_in,
                              void* d_out, int out_size) {
    const float4* deltas  = (const float4*)d_in[0];  // (B,64,64,36)
    const float*  labels  = (const float*)d_in[1];   // (B,64,64,9)
    const float4* anchors = (const float4*)d_in[2];  // (B,N,4)
    const float4* gt      = (const float4*)d_in[3];  // (B,64,4)
    float* out = (float*)d_out;

    (void)in_sizes; (void)n_in;

    static_assert(SEG * TPB == NANCH, "tiling must cover N exactly");

    size_t smem = 98304;   // bufA(64K) + regionC(32K)
    cudaFuncSetAttribute(nms_kernel, cudaFuncAttributeMaxDynamicSharedMemorySize, (int)smem);

    decode_kernel<<<(BATCH * NANCH + 255) / 256, 256>>>(deltas, anchors);
    nms_kernel<<<BATCH, TPB, smem>>>(labels, gt, out, out_size);
}

// round 14
// speedup vs baseline: 96.2395x; 1.0476x over previous
#include <cuda_runtime.h>
#include <math.h>

// Problem constants (fixed by the reference setup)
#define BATCH    16
#define NANCH    36864      // 64*64*9
#define TPB      1024
#define SEG      36         // NANCH / TPB
#define TOPN     300
#define NGT      64
#define NPOS     64
#define NBUCK    8192       // value-uniform score buckets
#define CAND_MAX 8192       // max candidates per tranche (bufA capacity)
#define TARGET   4096       // desired candidates in first tranche

typedef unsigned long long u64;
typedef unsigned int u32;

// Scratch (static device allocations — no runtime alloc)
__device__ float4 g_boxes[BATCH * NANCH];   // decoded (unclipped) boxes
__device__ u32    g_cum[BATCH * NBUCK];     // inclusive bucket prefix sums

// ---------------------------------------------------------------------------
// Bucket on VALUE (uniform for uniform scores), descending: bucket 0 = highest.
// ---------------------------------------------------------------------------
__device__ __forceinline__ int score_bucket(float s) {
    int i = (int)(s * (float)NBUCK);      // trunc toward zero: monotone overall
    i = max(0, min(NBUCK - 1, i));
    return (NBUCK - 1) - i;               // ascending bucket = descending score
}

// Total-order key: ascending key = descending score (sign-aware, any float range).
__device__ __forceinline__ u32 score_sortbits(float s) {
    u32 bb = __float_as_uint(s);
    u32 ord = bb ^ ((bb >> 31) ? 0xFFFFFFFFu : 0x80000000u);  // monotone in value
    return ~ord;                                              // ascending = value desc
}

// ---------------------------------------------------------------------------
// IoU exactly as reference: inter / (((areaA + areaB) - inter) + 1e-7)
// ---------------------------------------------------------------------------
__device__ __forceinline__ float iou_ref(float4 a, float4 b) {
    float yy1 = fmaxf(a.x, b.x);
    float xx1 = fmaxf(a.y, b.y);
    float yy2 = fminf(a.z, b.z);
    float xx2 = fminf(a.w, b.w);
    float ih  = fmaxf(yy2 - yy1, 0.0f);
    float iw  = fmaxf(xx2 - xx1, 0.0f);
    float inter = ih * iw;
    float areaA = (a.z - a.x) * (a.w - a.y);
    float areaB = (b.z - b.x) * (b.w - b.y);
    return inter / (((areaA + areaB) - inter) + 1e-7f);
}

// ---------------------------------------------------------------------------
// Suppression test vs sKept[lo..hi), unrolled x4 with deferred exit.
// max(i0..i3) >= 0.5  <=>  any ik >= 0.5 : identical decisions to scalar loop,
// but 4 independent LDS.128 + 4 independent IoUs pipeline instead of a
// serial load->compare->branch chain per kept box.
// ---------------------------------------------------------------------------
__device__ __forceinline__ bool supp_range(const float4* __restrict__ kept,
                                           int lo, int hi, float4 box) {
    int j = lo;
    for (; j + 4 <= hi; j += 4) {
        float4 k0 = kept[j + 0];
        float4 k1 = kept[j + 1];
        float4 k2 = kept[j + 2];
        float4 k3 = kept[j + 3];
        float i0 = iou_ref(k0, box);
        float i1 = iou_ref(k1, box);
        float i2 = iou_ref(k2, box);
        float i3 = iou_ref(k3, box);
        if (fmaxf(fmaxf(i0, i1), fmaxf(i2, i3)) >= 0.5f) return true;
    }
    for (; j < hi; j++)
        if (iou_ref(kept[j], box) >= 0.5f) return true;
    return false;
}

// exclusive block scan of per-thread totals (1024 threads, 32 warps).
__device__ __forceinline__ u32 block_excl_scan(u32 run, int lane, int warp, u32* sWarpSum) {
    u32 x = run;
    #pragma unroll
    for (int off = 1; off < 32; off <<= 1) {
        u32 y = __shfl_up_sync(0xFFFFFFFFu, x, off);
        if (lane >= off) x += y;
    }
    if (lane == 31) sWarpSum[warp] = x;
    __syncthreads();
    if (warp == 0) {
        u32 s = sWarpSum[lane];
        #pragma unroll
        for (int off = 1; off < 32; off <<= 1) {
            u32 y = __shfl_up_sync(0xFFFFFFFFu, s, off);
            if (lane >= off) s += y;
        }
        sWarpSum[lane] = s;
    }
    __syncthreads();
    u32 warpOff = (warp == 0) ? 0u : sWarpSum[warp - 1];
    return warpOff + x - run;
}

// ---------------------------------------------------------------------------
// Kernel 1: decode deltas -> boxes (mirrors reference op order exactly)
// ---------------------------------------------------------------------------
__global__ void decode_kernel(const float4* __restrict__ deltas,
                              const float4* __restrict__ anchors) {
    int i = blockIdx.x * blockDim.x + threadIdx.x;
    if (i >= BATCH * NANCH) return;
    float4 a = anchors[i];
    float4 d = deltas[i];
    float ah  = a.z - a.x;
    float aw  = a.w - a.y;
    float acy = a.x + 0.5f * ah;
    float acx = a.y + 0.5f * aw;
    float h   = expf(d.z) * ah;
    float w   = expf(d.w) * aw;
    float cy  = d.x * ah + acy;
    float cx  = d.y * aw + acx;
    float y1  = cy - 0.5f * h;
    float x1  = cx - 0.5f * w;
    g_boxes[i] = make_float4(y1, x1, y1 + h, x1 + w);
}

// ---------------------------------------------------------------------------
// Kernel 2 (fused): value-bucket histogram -> scatter + tiny per-bucket
// insertion sort -> warp-window greedy scan -> RoI selection + output.
// One CTA per batch.
// ---------------------------------------------------------------------------
__global__ __launch_bounds__(TPB, 1)
void nms_kernel(const float* __restrict__ labels,
                const float4* __restrict__ gt,
                float* __restrict__ out,
                int out_size) {
    extern __shared__ char dynsmem[];
    u64* bufA    = (u64*)dynsmem;                  // 64 KB: sorted candidates
    u32* regionC = (u32*)(dynsmem + 65536);        // 32 KB: hist / counters / select scratch

    __shared__ float4 sKept[TOPN];    // unclipped kept boxes (for suppression)
    __shared__ float4 sNms[TOPN];     // clipped kept boxes  (NMS output)
    __shared__ float4 sGtb[NGT];
    __shared__ u32    sWarpSum[32];
    __shared__ int    sKc;
    __shared__ int    sKlo, sKhi;

    const int b    = blockIdx.x;
    const int t    = threadIdx.x;
    const int lane = t & 31;
    const int warp = t >> 5;

    const float*  sc    = labels  + (size_t)b * NANCH;
    const float4* boxes = g_boxes + (size_t)b * NANCH;
    u32*          cum   = g_cum   + (size_t)b * NBUCK;

    // ---------------- phase 1: bucket histogram + prefix sums ----------------
    u32* hist = regionC;
    for (int i = t; i < NBUCK; i += TPB) hist[i] = 0u;
    __syncthreads();
    #pragma unroll
    for (int k = 0; k < SEG; k++) {
        int kb = score_bucket(sc[k * TPB + t]);         // coalesced read
        atomicAdd(&hist[kb], 1u);
    }
    __syncthreads();
    {   // inclusive prefix over NBUCK buckets (8 contiguous per thread)
        u32 loc[8], run = 0;
        #pragma unroll
        for (int i = 0; i < 8; i++) { run += hist[t * 8 + i]; loc[i] = run; }
        u32 excl = block_excl_scan(run, lane, warp, sWarpSum);
        #pragma unroll
        for (int i = 0; i < 8; i++) hist[t * 8 + i] = loc[i] + excl;
        __syncthreads();
        for (int i = t; i < NBUCK; i += TPB) cum[i] = hist[i];  // persist (regionC reused)
        __syncthreads();
    }

    // ---------------- tranche loop ----------------
    int kc   = 0;
    int curK = -1;
    u32 base = 0;

    while (kc < TOPN) {
        // --- choose K*: smallest j with >=TARGET candidates, capped at CAND_MAX ---
        if (t == 0) { sKlo = NBUCK; sKhi = NBUCK; }
        __syncthreads();
        for (int i = t; i < NBUCK; i += TPB) {
            if (i > curK) {
                u32 c = cum[i] - base;
                if (c >= (u32)TARGET)   atomicMin(&sKlo, i);
                if (c >  (u32)CAND_MAX) atomicMin(&sKhi, i);
            }
        }
        __syncthreads();
        int Kstar = min(sKlo, sKhi - 1);
        if (Kstar > NBUCK - 1) Kstar = NBUCK - 1;
        if (Kstar < curK + 1)  Kstar = curK + 1;   // pathological giant bucket
        int C = (int)(cum[Kstar] - base);          // exact tranche size (<= CAND_MAX)

        // --- init per-bucket write cursors to bucket start offsets ---
        u32* cnt = regionC;   // 8192 cursors
        for (int i = t; i < NBUCK; i += TPB)
            cnt[i] = (i > 0 ? cum[i - 1] : 0u) - base;   // only used for in-range buckets
        __syncthreads();

        // --- scatter candidates directly to bucket-grouped positions (coalesced read) ---
        #pragma unroll
        for (int k = 0; k < SEG; k++) {
            int e = k * TPB + t;
            float s = sc[e];
            int kb = score_bucket(s);
            if (kb > curK && kb <= Kstar) {
                u32 pos = atomicAdd(&cnt[kb], 1u);       // pos < C guaranteed by Kstar cap
                bufA[pos] = ((u64)score_sortbits(s) << 16) | (u32)e;
            }
        }
        __syncthreads();

        // --- per-bucket insertion sort on unique u64 key -> deterministic order.
        //     Value-uniform buckets: mean ~4.5 items -> O(k^2) trivial. ---
        for (int i = t; i < NBUCK; i += TPB) {
            if (i > curK && i <= Kstar) {
                int s = (int)((i > 0 ? cum[i - 1] : 0u) - base);
                int epos = (int)(cum[i] - base);
                for (int p = s + 1; p < epos; p++) {
                    u64 key = bufA[p];
                    int j = p - 1;
                    while (j >= s && bufA[j] > key) { bufA[j + 1] = bufA[j]; j--; }
                    bufA[j + 1] = key;
                }
            }
        }
        __syncthreads();
        // bufA[0..C): (score desc, idx asc)

        // --- warp-window greedy scan: 1 block barrier per 32 candidates ---
        for (int cb = 0; cb < C && kc < TOPN; cb += TPB) {
            int  pos  = cb + t;
            bool have = pos < C;
            u64  it   = have ? bufA[pos] : ~0ull;
            int  e    = (int)(it & 0xFFFFull);
            float4 myBox = make_float4(0.f, 0.f, 0.f, 0.f);
            if (have) myBox = boxes[e];
            bool alive = have;
            if (alive && supp_range(sKept, 0, kc, myBox)) alive = false;   // unrolled prefilter
            __syncthreads();   // sKept stable + alive computed before windows start

            for (int w = 0; w < 32 && kc < TOPN; w++) {
                if (warp == w) {
                    // intra-warp serial greedy over this window (sorted order)
                    u32 m = __ballot_sync(0xFFFFFFFFu, alive);
                    int kloc = kc;
                    while (m && kloc < TOPN) {
                        int win = __ffs((int)m) - 1;
                        float4 wb;
                        wb.x = __shfl_sync(0xFFFFFFFFu, myBox.x, win);
                        wb.y = __shfl_sync(0xFFFFFFFFu, myBox.y, win);
                        wb.z = __shfl_sync(0xFFFFFFFFu, myBox.z, win);
                        wb.w = __shfl_sync(0xFFFFFFFFu, myBox.w, win);
                        if (lane == win) {
                            sKept[kloc] = myBox;          // unclipped for suppression
                            float4 c;
                            c.x = fminf(fmaxf(myBox.x, 0.0f), 1.0f);
                            c.y = fminf(fmaxf(myBox.y, 0.0f), 1.0f);
                            c.z = fminf(fmaxf(myBox.z, 0.0f), 1.0f);
                            c.w = fminf(fmaxf(myBox.w, 0.0f), 1.0f);
                            sNms[kloc] = c;
                            alive = false;                 // explicit self-suppress
                        } else if (alive && iou_ref(wb, myBox) >= 0.5f) {
                            alive = false;
                        }
                        kloc++;
                        m = __ballot_sync(0xFFFFFFFFu, alive);
                    }
                    if (lane == 0) sKc = kloc;
                }
                __syncthreads();                           // publish sKept[kc..nk), sKc
                int nk = sKc;
                if (warp > w && alive && supp_range(sKept, kc, nk, myBox))  // unrolled catch-up
                    alive = false;
                kc = nk;
            }
        }

        // --- next tranche (exact refill) ---
        if (Kstar >= NBUCK - 1) break;                     // all boxes consumed
        curK = Kstar;
        base = cum[Kstar];
        __syncthreads();
    }

    // zero-fill remaining (invalid) NMS slots
    for (int s = kc + t; s < TOPN; s += TPB)
        sNms[s] = make_float4(0.f, 0.f, 0.f, 0.f);

    // ---------------- fused RoI selection (former select_kernel) ----------------
    float* merged = (float*)regionC;           // TOPN floats
    int*   gbest  = (int*)(regionC + 512);     // TOPN ints

    if (t < NGT) sGtb[t] = gt[b * NGT + t];
    __syncthreads();

    if (t < TOPN) {
        float4 A = sNms[t];
        float areaA = (A.z - A.x) * (A.w - A.y);
        float best = -INFINITY; int bj = 0;
        #pragma unroll 4
        for (int j = 0; j < NGT; j++) {
            float4 G = sGtb[j];
            float yy1 = fmaxf(A.x, G.x);
            float xx1 = fmaxf(A.y, G.y);
            float yy2 = fminf(A.z, G.z);
            float xx2 = fminf(A.w, G.w);
            float ih  = fmaxf(yy2 - yy1, 0.0f);
            float iw  = fmaxf(xx2 - xx1, 0.0f);
            float inter = ih * iw;
            float areaG = (G.z - G.x) * (G.w - G.y);
            float iou   = inter / (((areaA + areaG) - inter) + 1e-7f);
            if (iou > best) { best = iou; bj = j; }   // strict > == first occurrence
        }
        merged[t] = best;
        gbest[t]  = bj;
    }
    __syncthreads();

    if (t < TOPN) {
        float mv = merged[t];
        int rank = 0;
        for (int q = 0; q < TOPN; q++) {
            float qv = merged[q];
            rank += (qv > mv) || (qv == mv && q < t);   // stable: matches jnp.argsort
        }
        if (rank < NPOS) {
            float4 A = sNms[t];
            float* o = out + (size_t)b * 512 + (size_t)rank * 4;
            o[0] = A.x; o[1] = A.y; o[2] = A.z; o[3] = A.w;
            if (out_size >= BATCH * 512 + BATCH * NGT) {
                out[BATCH * 512 + b * NGT + rank] = (float)gbest[t];
            }
        }
    }

    // negatives: rows 64..127 are zeros
    for (int i = t; i < 256; i += TPB)
        out[(size_t)b * 512 + 256 + i] = 0.0f;
}

// ---------------------------------------------------------------------------
extern "C" void kernel_launch(void* const* d_in, const int* in_sizes, int n_in,
                              void* d_out, int out_size) {
    const float4* deltas  = (const float4*)d_in[0];  // (B,64,64,36)
    const float*  labels  = (const float*)d_in[1];   // (B,64,64,9)
    const float4* anchors = (const float4*)d_in[2];  // (B,N,4)
    const float4* gt      = (const float4*)d_in[3];  // (B,64,4)
    float* out = (float*)d_out;

    (void)in_sizes; (void)n_in;

    static_assert(SEG * TPB == NANCH, "tiling must cover N exactly");

    size_t smem = 98304;   // bufA(64K) + regionC(32K)
    cudaFuncSetAttribute(nms_kernel, cudaFuncAttributeMaxDynamicSharedMemorySize, (int)smem);

    decode_kernel<<<(BATCH * NANCH + 255) / 256, 256>>>(deltas, anchors);
    nms_kernel<<<BATCH, TPB, smem>>>(labels, gt, out, out_size);
}

// round 15
// speedup vs baseline: 100.8504x; 1.0479x over previous
#include <cuda_runtime.h>
#include <math.h>

// Problem constants (fixed by the reference setup)
#define BATCH    16
#define NANCH    36864      // 64*64*9
#define TPB      1024
#define SEG      36         // NANCH / TPB
#define TOPN     300
#define NGT      64
#define NPOS     64
#define NBUCK    8192       // value-uniform score buckets
#define CAND_MAX 8192       // max candidates per tranche (bufA capacity)
#define TARGET   4096       // desired candidates in first tranche

// hist kernel split
#define HSPLIT   8          // CTAs per batch for histogram
#define HTPB     512
#define HITEMS   (NANCH / HSPLIT / HTPB)   // 9

typedef unsigned long long u64;
typedef unsigned int u32;

// Scratch (static device allocations — no runtime alloc)
__device__ float4 g_boxes[BATCH * NANCH];   // decoded (unclipped) boxes
__device__ u32    g_hist[BATCH * NBUCK];    // raw bucket counts
__device__ u32    g_cum[BATCH * NBUCK];     // inclusive bucket prefix sums

// ---------------------------------------------------------------------------
// Bucket on VALUE (uniform for uniform scores), descending: bucket 0 = highest.
// ---------------------------------------------------------------------------
__device__ __forceinline__ int score_bucket(float s) {
    int i = (int)(s * (float)NBUCK);      // trunc toward zero: monotone overall
    i = max(0, min(NBUCK - 1, i));
    return (NBUCK - 1) - i;               // ascending bucket = descending score
}

// Total-order key: ascending key = descending score (sign-aware, any float range).
__device__ __forceinline__ u32 score_sortbits(float s) {
    u32 bb = __float_as_uint(s);
    u32 ord = bb ^ ((bb >> 31) ? 0xFFFFFFFFu : 0x80000000u);  // monotone in value
    return ~ord;                                              // ascending = value desc
}

// ---------------------------------------------------------------------------
// IoU exactly as reference: inter / (((areaA + areaB) - inter) + 1e-7)
// ---------------------------------------------------------------------------
__device__ __forceinline__ float iou_ref(float4 a, float4 b) {
    float yy1 = fmaxf(a.x, b.x);
    float xx1 = fmaxf(a.y, b.y);
    float yy2 = fminf(a.z, b.z);
    float xx2 = fminf(a.w, b.w);
    float ih  = fmaxf(yy2 - yy1, 0.0f);
    float iw  = fmaxf(xx2 - xx1, 0.0f);
    float inter = ih * iw;
    float areaA = (a.z - a.x) * (a.w - a.y);
    float areaB = (b.z - b.x) * (b.w - b.y);
    return inter / (((areaA + areaB) - inter) + 1e-7f);
}

// ---------------------------------------------------------------------------
// Suppression test vs sKept[lo..hi), unrolled x4 with deferred exit.
// ---------------------------------------------------------------------------
__device__ __forceinline__ bool supp_range(const float4* __restrict__ kept,
                                           int lo, int hi, float4 box) {
    int j = lo;
    for (; j + 4 <= hi; j += 4) {
        float4 k0 = kept[j + 0];
        float4 k1 = kept[j + 1];
        float4 k2 = kept[j + 2];
        float4 k3 = kept[j + 3];
        float i0 = iou_ref(k0, box);
        float i1 = iou_ref(k1, box);
        float i2 = iou_ref(k2, box);
        float i3 = iou_ref(k3, box);
        if (fmaxf(fmaxf(i0, i1), fmaxf(i2, i3)) >= 0.5f) return true;
    }
    for (; j < hi; j++)
        if (iou_ref(kept[j], box) >= 0.5f) return true;
    return false;
}

// exclusive block scan of per-thread totals (1024 threads, 32 warps).
__device__ __forceinline__ u32 block_excl_scan(u32 run, int lane, int warp, u32* sWarpSum) {
    u32 x = run;
    #pragma unroll
    for (int off = 1; off < 32; off <<= 1) {
        u32 y = __shfl_up_sync(0xFFFFFFFFu, x, off);
        if (lane >= off) x += y;
    }
    if (lane == 31) sWarpSum[warp] = x;
    __syncthreads();
    if (warp == 0) {
        u32 s = sWarpSum[lane];
        #pragma unroll
        for (int off = 1; off < 32; off <<= 1) {
            u32 y = __shfl_up_sync(0xFFFFFFFFu, s, off);
            if (lane >= off) s += y;
        }
        sWarpSum[lane] = s;
    }
    __syncthreads();
    u32 warpOff = (warp == 0) ? 0u : sWarpSum[warp - 1];
    return warpOff + x - run;
}

// ---------------------------------------------------------------------------
// Kernel 1: decode deltas -> boxes (mirrors reference op order exactly)
// ---------------------------------------------------------------------------
__global__ void decode_kernel(const float4* __restrict__ deltas,
                              const float4* __restrict__ anchors) {
    int i = blockIdx.x * blockDim.x + threadIdx.x;
    if (i >= BATCH * NANCH) return;
    float4 a = anchors[i];
    float4 d = deltas[i];
    float ah  = a.z - a.x;
    float aw  = a.w - a.y;
    float acy = a.x + 0.5f * ah;
    float acx = a.y + 0.5f * aw;
    float h   = expf(d.z) * ah;
    float w   = expf(d.w) * aw;
    float cy  = d.x * ah + acy;
    float cx  = d.y * aw + acx;
    float y1  = cy - 0.5f * h;
    float x1  = cx - 0.5f * w;
    g_boxes[i] = make_float4(y1, x1, y1 + h, x1 + w);
}

// ---------------------------------------------------------------------------
// Kernel 1b: zero g_hist (required per graph replay)
// ---------------------------------------------------------------------------
__global__ void zero_kernel() {
    int i = blockIdx.x * blockDim.x + threadIdx.x;
    if (i < BATCH * NBUCK) g_hist[i] = 0u;
}

// ---------------------------------------------------------------------------
// Kernel 1c: parallel histogram — HSPLIT CTAs per batch, global RED atomics.
// Deterministic: u32 addition is commutative.
// ---------------------------------------------------------------------------
__global__ void hist_kernel(const float* __restrict__ labels) {
    int b   = blockIdx.x / HSPLIT;
    int seg = blockIdx.x % HSPLIT;
    const float* sc = labels + (size_t)b * NANCH + (size_t)seg * (NANCH / HSPLIT);
    u32* hist = g_hist + (size_t)b * NBUCK;
    int t = threadIdx.x;
    #pragma unroll
    for (int k = 0; k < HITEMS; k++) {
        int kb = score_bucket(sc[k * HTPB + t]);    // coalesced
        atomicAdd(&hist[kb], 1u);                   // RED (no return), spread addrs
    }
}

// ---------------------------------------------------------------------------
// Kernel 1d: inclusive prefix over NBUCK buckets per batch -> g_cum
// ---------------------------------------------------------------------------
__global__ __launch_bounds__(TPB, 1)
void prefix_kernel() {
    __shared__ u32 sWarpSum[32];
    const int b    = blockIdx.x;
    const int t    = threadIdx.x;
    const int lane = t & 31;
    const int warp = t >> 5;
    const u32* hist = g_hist + (size_t)b * NBUCK;
    u32*       cum  = g_cum  + (size_t)b * NBUCK;

    u32 loc[8], run = 0;
    #pragma unroll
    for (int i = 0; i < 8; i++) { run += hist[t * 8 + i]; loc[i] = run; }
    u32 excl = block_excl_scan(run, lane, warp, sWarpSum);
    #pragma unroll
    for (int i = 0; i < 8; i++) cum[t * 8 + i] = loc[i] + excl;
}

// ---------------------------------------------------------------------------
// Kernel 2: tranche scatter + tiny per-bucket insertion sort -> warp-window
// greedy scan -> RoI selection + output. One CTA per batch. (phase 1 removed)
// ---------------------------------------------------------------------------
__global__ __launch_bounds__(TPB, 1)
void nms_kernel(const float* __restrict__ labels,
                const float4* __restrict__ gt,
                float* __restrict__ out,
                int out_size) {
    extern __shared__ char dynsmem[];
    u64* bufA    = (u64*)dynsmem;                  // 64 KB: sorted candidates
    u32* regionC = (u32*)(dynsmem + 65536);        // 32 KB: counters / select scratch

    __shared__ float4 sKept[TOPN];    // unclipped kept boxes (for suppression)
    __shared__ float4 sNms[TOPN];     // clipped kept boxes  (NMS output)
    __shared__ float4 sGtb[NGT];
    __shared__ int    sKc;
    __shared__ int    sKlo, sKhi;

    const int b    = blockIdx.x;
    const int t    = threadIdx.x;
    const int lane = t & 31;
    const int warp = t >> 5;

    const float*  sc    = labels  + (size_t)b * NANCH;
    const float4* boxes = g_boxes + (size_t)b * NANCH;
    const u32*    cum   = g_cum   + (size_t)b * NBUCK;

    // ---------------- tranche loop ----------------
    int kc   = 0;
    int curK = -1;
    u32 base = 0;

    while (kc < TOPN) {
        // --- choose K*: smallest j with >=TARGET candidates, capped at CAND_MAX ---
        if (t == 0) { sKlo = NBUCK; sKhi = NBUCK; }
        __syncthreads();
        for (int i = t; i < NBUCK; i += TPB) {
            if (i > curK) {
                u32 c = cum[i] - base;
                if (c >= (u32)TARGET)   atomicMin(&sKlo, i);
                if (c >  (u32)CAND_MAX) atomicMin(&sKhi, i);
            }
        }
        __syncthreads();
        int Kstar = min(sKlo, sKhi - 1);
        if (Kstar > NBUCK - 1) Kstar = NBUCK - 1;
        if (Kstar < curK + 1)  Kstar = curK + 1;   // pathological giant bucket
        int C = (int)(cum[Kstar] - base);          // exact tranche size (<= CAND_MAX)

        // --- init per-bucket write cursors to bucket start offsets ---
        u32* cnt = regionC;   // 8192 cursors
        for (int i = t; i < NBUCK; i += TPB)
            cnt[i] = (i > 0 ? cum[i - 1] : 0u) - base;   // only used for in-range buckets
        __syncthreads();

        // --- scatter candidates directly to bucket-grouped positions (coalesced read) ---
        #pragma unroll
        for (int k = 0; k < SEG; k++) {
            int e = k * TPB + t;
            float s = sc[e];
            int kb = score_bucket(s);
            if (kb > curK && kb <= Kstar) {
                u32 pos = atomicAdd(&cnt[kb], 1u);       // pos < C guaranteed by Kstar cap
                bufA[pos] = ((u64)score_sortbits(s) << 16) | (u32)e;
            }
        }
        __syncthreads();

        // --- per-bucket insertion sort on unique u64 key -> deterministic order. ---
        for (int i = t; i < NBUCK; i += TPB) {
            if (i > curK && i <= Kstar) {
                int s = (int)((i > 0 ? cum[i - 1] : 0u) - base);
                int epos = (int)(cum[i] - base);
                for (int p = s + 1; p < epos; p++) {
                    u64 key = bufA[p];
                    int j = p - 1;
                    while (j >= s && bufA[j] > key) { bufA[j + 1] = bufA[j]; j--; }
                    bufA[j + 1] = key;
                }
            }
        }
        __syncthreads();
        // bufA[0..C): (score desc, idx asc)

        // --- warp-window greedy scan: 1 block barrier per 32 candidates ---
        for (int cb = 0; cb < C && kc < TOPN; cb += TPB) {
            int  pos  = cb + t;
            bool have = pos < C;
            u64  it   = have ? bufA[pos] : ~0ull;
            int  e    = (int)(it & 0xFFFFull);
            float4 myBox = make_float4(0.f, 0.f, 0.f, 0.f);
            if (have) myBox = boxes[e];
            bool alive = have;
            if (alive && supp_range(sKept, 0, kc, myBox)) alive = false;   // prefilter
            __syncthreads();   // sKept stable + alive computed before windows start

            for (int w = 0; w < 32 && kc < TOPN; w++) {
                if (warp == w) {
                    // intra-warp serial greedy over this window (sorted order)
                    u32 m = __ballot_sync(0xFFFFFFFFu, alive);
                    int kloc = kc;
                    while (m && kloc < TOPN) {
                        int win = __ffs((int)m) - 1;
                        float4 wb;
                        wb.x = __shfl_sync(0xFFFFFFFFu, myBox.x, win);
                        wb.y = __shfl_sync(0xFFFFFFFFu, myBox.y, win);
                        wb.z = __shfl_sync(0xFFFFFFFFu, myBox.z, win);
                        wb.w = __shfl_sync(0xFFFFFFFFu, myBox.w, win);
                        if (lane == win) {
                            sKept[kloc] = myBox;          // unclipped for suppression
                            float4 c;
                            c.x = fminf(fmaxf(myBox.x, 0.0f), 1.0f);
                            c.y = fminf(fmaxf(myBox.y, 0.0f), 1.0f);
                            c.z = fminf(fmaxf(myBox.z, 0.0f), 1.0f);
                            c.w = fminf(fmaxf(myBox.w, 0.0f), 1.0f);
                            sNms[kloc] = c;
                            alive = false;                 // explicit self-suppress
                        } else if (alive && iou_ref(wb, myBox) >= 0.5f) {
                            alive = false;
                        }
                        kloc++;
                        m = __ballot_sync(0xFFFFFFFFu, alive);
                    }
                    if (lane == 0) sKc = kloc;
                }
                __syncthreads();                           // publish sKept[kc..nk), sKc
                int nk = sKc;
                if (warp > w && alive && supp_range(sKept, kc, nk, myBox))  // catch-up
                    alive = false;
                kc = nk;
            }
        }

        // --- next tranche (exact refill) ---
        if (Kstar >= NBUCK - 1) break;                     // all boxes consumed
        curK = Kstar;
        base = cum[Kstar];
        __syncthreads();
    }

    // zero-fill remaining (invalid) NMS slots
    for (int s = kc + t; s < TOPN; s += TPB)
        sNms[s] = make_float4(0.f, 0.f, 0.f, 0.f);

    // ---------------- fused RoI selection ----------------
    float* merged = (float*)regionC;           // TOPN floats
    int*   gbest  = (int*)(regionC + 512);     // TOPN ints

    if (t < NGT) sGtb[t] = gt[b * NGT + t];
    __syncthreads();

    if (t < TOPN) {
        float4 A = sNms[t];
        float areaA = (A.z - A.x) * (A.w - A.y);
        float best = -INFINITY; int bj = 0;
        #pragma unroll 4
        for (int j = 0; j < NGT; j++) {
            float4 G = sGtb[j];
            float yy1 = fmaxf(A.x, G.x);
            float xx1 = fmaxf(A.y, G.y);
            float yy2 = fminf(A.z, G.z);
            float xx2 = fminf(A.w, G.w);
            float ih  = fmaxf(yy2 - yy1, 0.0f);
            float iw  = fmaxf(xx2 - xx1, 0.0f);
            float inter = ih * iw;
            float areaG = (G.z - G.x) * (G.w - G.y);
            float iou   = inter / (((areaA + areaG) - inter) + 1e-7f);
            if (iou > best) { best = iou; bj = j; }   // strict > == first occurrence
        }
        merged[t] = best;
        gbest[t]  = bj;
    }
    __syncthreads();

    if (t < TOPN) {
        float mv = merged[t];
        int rank = 0;
        for (int q = 0; q < TOPN; q++) {
            float qv = merged[q];
            rank += (qv > mv) || (qv == mv && q < t);   // stable: matches jnp.argsort
        }
        if (rank < NPOS) {
            float4 A = sNms[t];
            float* o = out + (size_t)b * 512 + (size_t)rank * 4;
            o[0] = A.x; o[1] = A.y; o[2] = A.z; o[3] = A.w;
            if (out_size >= BATCH * 512 + BATCH * NGT) {
                out[BATCH * 512 + b * NGT + rank] = (float)gbest[t];
            }
        }
    }

    // negatives: rows 64..127 are zeros
    for (int i = t; i < 256; i += TPB)
        out[(size_t)b * 512 + 256 + i] = 0.0f;
}

// ---------------------------------------------------------------------------
extern "C" void kernel_launch(void* const* d_in, const int* in_sizes, int n_in,
                              void* d_out, int out_size) {
    const float4* deltas  = (const float4*)d_in[0];  // (B,64,64,36)
    const float*  labels  = (const float*)d_in[1];   // (B,64,64,9)
    const float4* anchors = (const float4*)d_in[2];  // (B,N,4)
    const float4* gt      = (const float4*)d_in[3];  // (B,64,4)
    float* out = (float*)d_out;

    (void)in_sizes; (void)n_in;

    static_assert(SEG * TPB == NANCH, "tiling must cover N exactly");
    static_assert(HITEMS * HTPB * HSPLIT == NANCH, "hist tiling");

    size_t smem = 98304;   // bufA(64K) + regionC(32K)
    cudaFuncSetAttribute(nms_kernel, cudaFuncAttributeMaxDynamicSharedMemorySize, (int)smem);

    decode_kernel<<<(BATCH * NANCH + 255) / 256, 256>>>(deltas, anchors);
    zero_kernel<<<(BATCH * NBUCK + 255) / 256, 256>>>();
    hist_kernel<<<BATCH * HSPLIT, HTPB>>>(labels);
    prefix_kernel<<<BATCH, TPB>>>();
    nms_kernel<<<BATCH, TPB, smem>>>(labels, gt, out, out_size);
}